// round 7
// baseline (speedup 1.0000x reference)
#include <cuda_runtime.h>
#include <math.h>

#define S_TOK 4096
#define DE 256
#define DC 64
#define DIN 320
#define DM 64
#define DEPTH 4
#define DTs 0.1f
#define SCALE 0.0625f   /* 1/sqrt(256) */
#define KSPLIT 2

/* output layout offsets (flattened concat of the reference tuple, float32) */
#define E_OFF  (S_TOK*DE)            /* 1048576 */
#define P_OFF  (E_OFF + S_TOK)
#define G_OFF  (P_OFF + S_TOK)
#define M_OFF  (G_OFF + S_TOK)       /* 1060864 */
#define C_OFF  (M_OFF + S_TOK*DM)    /* 1323008 */
#define L_OFF  (C_OFF + S_TOK*DM)    /* 1585152 */
#define A_OFF  (L_OFF + S_TOK)       /* 1589248 */
#define D_OFF  (A_OFF + S_TOK)       /* 1593344 */

/* persistent state (device globals: no allocation allowed) */
__device__ float g_e[S_TOK*DE];
__device__ float g_q[S_TOK*DE];
__device__ float g_k[S_TOK*DE];
__device__ float g_v[S_TOK*DE];
__device__ float g_m[S_TOK*DM];      /* raw m */
__device__ float g_mt[S_TOK*DM];     /* m~ = l*m (combined membrane*lifespan mask) */
__device__ float g_E[S_TOK];
__device__ float g_P[S_TOK];
__device__ float g_G[S_TOK];
__device__ float g_l[S_TOK];
__device__ float g_hpart[KSPLIT][S_TOK*DE];
__device__ float g_Mpart[KSPLIT][S_TOK];
__device__ float g_Lpart[KSPLIT][S_TOK];
__device__ int   g_alive_count;

/* ------------------------------------------------------------------ init */
__global__ void init_kernel(const float* __restrict__ e, const float* __restrict__ Ein,
                            const float* __restrict__ Pin, const float* __restrict__ Gin,
                            const float* __restrict__ min_, const float* __restrict__ lin)
{
    int i = blockIdx.x * 256 + threadIdx.x;      /* grid covers S_TOK*DE exactly */
    g_e[i] = e[i];
    if (i < S_TOK*DM) {
        float mv = min_[i];
        g_m[i]  = mv;
        g_mt[i] = mv * lin[i / DM];
    }
    if (i < S_TOK) {
        g_l[i] = lin[i]; g_E[i] = Ein[i]; g_P[i] = Pin[i]; g_G[i] = Gin[i];
    }
    if (i == 0) g_alive_count = 0;
}

/* ------------------------------------------------------- QKV projections */
/* out = [e|c] @ W + b ; M=4096 K=320 N=256 ; block 64x64, 256 thr, 4x4 micro */
__global__ void __launch_bounds__(256) qkv_kernel(
    const float* __restrict__ cin,
    const float* __restrict__ wq, const float* __restrict__ bq,
    const float* __restrict__ wk, const float* __restrict__ bk,
    const float* __restrict__ wv, const float* __restrict__ bv, int layer)
{
    __shared__ float sA[16][68];   /* x tile transposed [k][m], padded */
    __shared__ float sB[16][64];   /* W tile [k][n] */
    const int tid = threadIdx.x;
    const int m0 = blockIdx.x * 64, n0 = blockIdx.y * 64;
    const int which = blockIdx.z;
    const float* W = (which == 0 ? wq : which == 1 ? wk : wv) + (size_t)layer * DIN * DE;
    const float* B = (which == 0 ? bq : which == 1 ? bk : bv) + layer * DE;
    float* out = (which == 0 ? g_q : which == 1 ? g_k : g_v);
    const int ty = tid >> 4, tx = tid & 15;

    float acc[4][4] = {};
    for (int kt = 0; kt < 20; kt++) {
        const int k0 = kt * 16;
        __syncthreads();
        for (int idx = tid; idx < 1024; idx += 256) {
            int mm = idx >> 4, kk = idx & 15;
            float v;
            if (k0 < 256) v = g_e[(m0 + mm) * DE + k0 + kk];
            else          v = cin[(m0 + mm) * DC + (k0 - 256) + kk];
            sA[kk][mm] = v;
        }
        for (int idx = tid; idx < 1024; idx += 256) {
            int kk = idx >> 6, nn = idx & 63;
            sB[kk][nn] = W[(size_t)(k0 + kk) * DE + n0 + nn];
        }
        __syncthreads();
        #pragma unroll
        for (int kk = 0; kk < 16; kk++) {
            float4 a = *(const float4*)&sA[kk][4 * ty];
            float4 b = *(const float4*)&sB[kk][4 * tx];
            acc[0][0] += a.x*b.x; acc[0][1] += a.x*b.y; acc[0][2] += a.x*b.z; acc[0][3] += a.x*b.w;
            acc[1][0] += a.y*b.x; acc[1][1] += a.y*b.y; acc[1][2] += a.y*b.z; acc[1][3] += a.y*b.w;
            acc[2][0] += a.z*b.x; acc[2][1] += a.z*b.y; acc[2][2] += a.z*b.z; acc[2][3] += a.z*b.w;
            acc[3][0] += a.w*b.x; acc[3][1] += a.w*b.y; acc[3][2] += a.w*b.z; acc[3][3] += a.w*b.w;
        }
    }
    #pragma unroll
    for (int i = 0; i < 4; i++) {
        float4 r;
        r.x = acc[i][0] + B[n0 + 4*tx + 0];
        r.y = acc[i][1] + B[n0 + 4*tx + 1];
        r.z = acc[i][2] + B[n0 + 4*tx + 2];
        r.w = acc[i][3] + B[n0 + 4*tx + 3];
        *(float4*)(out + (size_t)(m0 + 4*ty + i) * DE + n0 + 4*tx) = r;
    }
}

/* ----------------------------------------------------- fused attention */
/* BM=64 queries x (S/KSPLIT) keys, online softmax, unnormalized partials. */
#define ATTN_SMEM_FLOATS (64*260 + 64*260 + 64*128 + 64*68 + 64*68 + 64*64)
#define ATTN_SMEM_BYTES  (ATTN_SMEM_FLOATS * 4)

__global__ void __launch_bounds__(256, 1) attn_kernel()
{
    extern __shared__ float sm[];
    float* sQ  = sm;                 /* [64][260] q tile, row-major padded   */
    float* sK  = sQ  + 64*260;       /* [64][260] k tile                     */
    float* sV  = sK  + 64*260;       /* [64][128] v half-tile                */
    float* sMq = sV  + 64*128;       /* [64][68]  m~ query tile              */
    float* sMk = sMq + 64*68;        /* [64][68]  m~ key tile                */
    float* sP  = sMk + 64*68;        /* [64][64]  scores / probabilities     */

    const int tid  = threadIdx.x;
    const int row0 = blockIdx.x * 64;
    const int ks   = blockIdx.y;
    const int key_base = ks * (S_TOK / KSPLIT);
    const int g = tid >> 5, lane = tid & 31;
    const int ty = tid >> 4, tx = tid & 15;

    for (int idx = tid; idx < 64*64; idx += 256) {
        int r = idx >> 6, d4 = (idx & 63) << 2;
        *(float4*)(sQ + r*260 + d4) = *(const float4*)(g_q + (size_t)(row0 + r)*DE + d4);
    }
    for (int idx = tid; idx < 64*16; idx += 256) {
        int r = idx >> 4, d4 = (idx & 15) << 2;
        *(float4*)(sMq + r*68 + d4) = *(const float4*)(g_mt + (size_t)(row0 + r)*DM + d4);
    }

    float acc[8][8];
    #pragma unroll
    for (int i = 0; i < 8; i++)
        #pragma unroll
        for (int j = 0; j < 8; j++) acc[i][j] = 0.f;
    float rowM[8], rowL[8];
    #pragma unroll
    for (int i = 0; i < 8; i++) { rowM[i] = -INFINITY; rowL[i] = 0.f; }

    for (int kt = 0; kt < (S_TOK / KSPLIT) / 64; kt++) {
        const int key0 = key_base + kt * 64;
        __syncthreads();
        for (int idx = tid; idx < 64*64; idx += 256) {
            int r = idx >> 6, d4 = (idx & 63) << 2;
            *(float4*)(sK + r*260 + d4) = *(const float4*)(g_k + (size_t)(key0 + r)*DE + d4);
        }
        for (int idx = tid; idx < 64*16; idx += 256) {
            int r = idx >> 4, d4 = (idx & 15) << 2;
            *(float4*)(sMk + r*68 + d4) = *(const float4*)(g_mt + (size_t)(key0 + r)*DM + d4);
        }
        for (int idx = tid; idx < 64*32; idx += 256) {
            int r = idx >> 5, d4 = (idx & 31) << 2;
            *(float4*)(sV + r*128 + d4) = *(const float4*)(g_v + (size_t)(key0 + r)*DE + d4);
        }
        __syncthreads();

        /* score phase: q.k over 256 dims, m~.m~ over 64 dims */
        float sqk[4][4] = {}; float smm[4][4] = {};
        {
            const float* qp = sQ + 4*ty*260;
            #pragma unroll 4
            for (int d = 0; d < DE; d += 4) {
                float4 qa[4], kb[4];
                #pragma unroll
                for (int i = 0; i < 4; i++) qa[i] = *(const float4*)(qp + i*260 + d);
                #pragma unroll
                for (int j = 0; j < 4; j++) kb[j] = *(const float4*)(sK + (tx + 16*j)*260 + d);
                #pragma unroll
                for (int i = 0; i < 4; i++)
                    #pragma unroll
                    for (int j = 0; j < 4; j++)
                        sqk[i][j] += qa[i].x*kb[j].x + qa[i].y*kb[j].y
                                   + qa[i].z*kb[j].z + qa[i].w*kb[j].w;
            }
            const float* mp = sMq + 4*ty*68;
            #pragma unroll 4
            for (int d = 0; d < DM; d += 4) {
                float4 qa[4], kb[4];
                #pragma unroll
                for (int i = 0; i < 4; i++) qa[i] = *(const float4*)(mp + i*68 + d);
                #pragma unroll
                for (int j = 0; j < 4; j++) kb[j] = *(const float4*)(sMk + (tx + 16*j)*68 + d);
                #pragma unroll
                for (int i = 0; i < 4; i++)
                    #pragma unroll
                    for (int j = 0; j < 4; j++)
                        smm[i][j] += qa[i].x*kb[j].x + qa[i].y*kb[j].y
                                   + qa[i].z*kb[j].z + qa[i].w*kb[j].w;
            }
        }
        #pragma unroll
        for (int i = 0; i < 4; i++)
            #pragma unroll
            for (int j = 0; j < 4; j++)
                sP[(4*ty + i)*64 + tx + 16*j] = sqk[i][j] * SCALE * smm[i][j];
        __syncthreads();

        /* online softmax: warp g owns rows 8g..8g+7 */
        #pragma unroll
        for (int i = 0; i < 8; i++) {
            const int r = 8*g + i;
            float s0 = sP[r*64 + lane];
            float s1 = sP[r*64 + 32 + lane];
            float tmax = fmaxf(s0, s1);
            #pragma unroll
            for (int off = 16; off; off >>= 1)
                tmax = fmaxf(tmax, __shfl_xor_sync(0xffffffffu, tmax, off));
            float newM = fmaxf(rowM[i], tmax);
            float p0 = __expf(s0 - newM);
            float p1 = __expf(s1 - newM);
            float corr = __expf(rowM[i] - newM);
            float ts = p0 + p1;
            #pragma unroll
            for (int off = 16; off; off >>= 1)
                ts += __shfl_xor_sync(0xffffffffu, ts, off);
            rowL[i] = rowL[i] * corr + ts;
            rowM[i] = newM;
            sP[r*64 + lane] = p0;
            sP[r*64 + 32 + lane] = p1;
            #pragma unroll
            for (int jj = 0; jj < 8; jj++) acc[i][jj] *= corr;
        }
        /* no sync needed: each warp reads only its own sP rows below */

        /* AV half 0 (cols 0..127) */
        #pragma unroll 2
        for (int t = 0; t < 64; t += 4) {
            float4 pv[8];
            #pragma unroll
            for (int i = 0; i < 8; i++) pv[i] = *(const float4*)(sP + (8*g + i)*64 + t);
            #pragma unroll
            for (int tt = 0; tt < 4; tt++) {
                float4 vv = *(const float4*)(sV + (t + tt)*128 + 4*lane);
                #pragma unroll
                for (int i = 0; i < 8; i++) {
                    float p = (tt == 0) ? pv[i].x : (tt == 1) ? pv[i].y : (tt == 2) ? pv[i].z : pv[i].w;
                    acc[i][0] += p*vv.x; acc[i][1] += p*vv.y;
                    acc[i][2] += p*vv.z; acc[i][3] += p*vv.w;
                }
            }
        }
        __syncthreads();
        for (int idx = tid; idx < 64*32; idx += 256) {
            int r = idx >> 5, d4 = (idx & 31) << 2;
            *(float4*)(sV + r*128 + d4) = *(const float4*)(g_v + (size_t)(key0 + r)*DE + 128 + d4);
        }
        __syncthreads();
        /* AV half 1 (cols 128..255) */
        #pragma unroll 2
        for (int t = 0; t < 64; t += 4) {
            float4 pv[8];
            #pragma unroll
            for (int i = 0; i < 8; i++) pv[i] = *(const float4*)(sP + (8*g + i)*64 + t);
            #pragma unroll
            for (int tt = 0; tt < 4; tt++) {
                float4 vv = *(const float4*)(sV + (t + tt)*128 + 4*lane);
                #pragma unroll
                for (int i = 0; i < 8; i++) {
                    float p = (tt == 0) ? pv[i].x : (tt == 1) ? pv[i].y : (tt == 2) ? pv[i].z : pv[i].w;
                    acc[i][4] += p*vv.x; acc[i][5] += p*vv.y;
                    acc[i][6] += p*vv.z; acc[i][7] += p*vv.w;
                }
            }
        }
    }

    /* write unnormalized partials + (M, L) */
    #pragma unroll
    for (int i = 0; i < 8; i++) {
        const int row = row0 + 8*g + i;
        float* hp = &g_hpart[ks][(size_t)row * DE];
        *(float4*)(hp + 4*lane)       = make_float4(acc[i][0], acc[i][1], acc[i][2], acc[i][3]);
        *(float4*)(hp + 128 + 4*lane) = make_float4(acc[i][4], acc[i][5], acc[i][6], acc[i][7]);
    }
    #pragma unroll
    for (int i = 0; i < 8; i++) {
        if (lane == i) {
            g_Mpart[ks][row0 + 8*g + i] = rowM[i];
            g_Lpart[ks][row0 + 8*g + i] = rowL[i];
        }
    }
}

/* ----------------------------------------- combine splits + ODE update */
__global__ void combine_kernel(const float* __restrict__ alpha, const float* __restrict__ beta,
                               const float* __restrict__ gamma, const float* __restrict__ basal,
                               int layer)
{
    const int s = blockIdx.x, tid = threadIdx.x;
    const float M0 = g_Mpart[0][s], M1 = g_Mpart[1][s];
    const float L0 = g_Lpart[0][s], L1 = g_Lpart[1][s];
    const float M  = fmaxf(M0, M1);
    const float c0 = __expf(M0 - M), c1 = __expf(M1 - M);
    const float invL = 1.0f / (L0 * c0 + L1 * c1);
    const float h = (g_hpart[0][(size_t)s*DE + tid] * c0
                   + g_hpart[1][(size_t)s*DE + tid] * c1) * invL;
    g_e[(size_t)s*DE + tid] += h;

    float part = h * h;
    #pragma unroll
    for (int off = 16; off; off >>= 1) part += __shfl_xor_sync(0xffffffffu, part, off);
    __shared__ float red[8];
    __shared__ float sc[2];
    if ((tid & 31) == 0) red[tid >> 5] = part;
    __syncthreads();
    if (tid == 0) {
        float S_in = red[0]+red[1]+red[2]+red[3]+red[4]+red[5]+red[6]+red[7];
        float E = g_E[s], P = g_P[s], Gv = g_G[s], l = g_l[s];
        float PE = P * E;
        float P_new = fmaxf(P + (alpha[layer]*S_in - beta[layer]*PE) * DTs, 0.f);
        float E_new = fmaxf(E + (basal[layer] - gamma[layer]*PE) * DTs, 0.f);
        float m_t = 1.f / (1.f + expf(-(E_new - P_new)));
        Gv += (0.1f*E_new - 0.5f*P_new) * DTs;
        float ldec = 0.01f + 0.5f*fmaxf(P_new - 2.f, 0.f);
        float l_new = fminf(fmaxf(l - ldec*DTs, 0.f), 1.f);
        g_E[s] = E_new; g_P[s] = P_new; g_G[s] = Gv; g_l[s] = l_new;
        sc[0] = m_t; sc[1] = l_new;
    }
    __syncthreads();
    if (tid < DM) {
        float mo = g_m[s*DM + tid];
        float mn = 0.9f*mo + 0.1f*sc[0];
        g_m[s*DM + tid]  = mn;
        g_mt[s*DM + tid] = sc[1] * mn;
    }
}

/* -------------------------------------------------------- final output */
__global__ void output_kernel(const float* __restrict__ cin, float* __restrict__ out)
{
    const int s = blockIdx.x, tid = threadIdx.x;
    const float l = g_l[s];
    const bool alive = (l > 0.05f);
    const float af = alive ? 1.f : 0.f;
    out[(size_t)s*DE + tid] = g_e[(size_t)s*DE + tid] * af;
    if (tid < DM) {
        out[M_OFF + s*DM + tid] = g_m[s*DM + tid] * af;
        out[C_OFF + s*DM + tid] = cin[s*DM + tid] * af;
    }
    if (tid == 0) {
        out[E_OFF + s] = g_E[s] * af;
        out[P_OFF + s] = g_P[s] * af;
        out[G_OFF + s] = g_G[s] * af;
        out[L_OFF + s] = l * af;
        out[A_OFF + s] = af;
        if (alive) atomicAdd(&g_alive_count, 1);
    }
}

__global__ void died_kernel(float* __restrict__ out)
{
    out[D_OFF] = (float)(S_TOK - g_alive_count);
}

/* -------------------------------------------------------------- launch */
extern "C" void kernel_launch(void* const* d_in, const int* in_sizes, int n_in,
                              void* d_out, int out_size)
{
    const float* e     = (const float*)d_in[0];
    const float* Ein   = (const float*)d_in[1];
    const float* Pin   = (const float*)d_in[2];
    const float* Gin   = (const float*)d_in[3];
    const float* m     = (const float*)d_in[4];
    const float* c     = (const float*)d_in[5];
    const float* l     = (const float*)d_in[6];
    const float* wq    = (const float*)d_in[7];
    const float* bq    = (const float*)d_in[8];
    const float* wk    = (const float*)d_in[9];
    const float* bk    = (const float*)d_in[10];
    const float* wv    = (const float*)d_in[11];
    const float* bv    = (const float*)d_in[12];
    const float* alpha = (const float*)d_in[13];
    const float* beta  = (const float*)d_in[14];
    const float* gamma = (const float*)d_in[15];
    const float* basal = (const float*)d_in[16];
    float* out = (float*)d_out;

    cudaFuncSetAttribute(attn_kernel, cudaFuncAttributeMaxDynamicSharedMemorySize,
                         ATTN_SMEM_BYTES);

    init_kernel<<<S_TOK*DE/256, 256>>>(e, Ein, Pin, Gin, m, l);
    for (int layer = 0; layer < DEPTH; layer++) {
        qkv_kernel<<<dim3(S_TOK/64, DE/64, 3), 256>>>(c, wq, bq, wk, bk, wv, bv, layer);
        attn_kernel<<<dim3(S_TOK/64, KSPLIT), 256, ATTN_SMEM_BYTES>>>();
        combine_kernel<<<S_TOK, 256>>>(alpha, beta, gamma, basal, layer);
    }
    output_kernel<<<S_TOK, 256>>>(c, out);
    died_kernel<<<1, 1>>>(out);
}

// round 9
// speedup vs baseline: 2.1220x; 2.1220x over previous
#include <cuda_runtime.h>
#include <cuda_bf16.h>
#include <math.h>
#include <stdint.h>

#define S_TOK 4096
#define DE 256
#define DC 64
#define DIN 320
#define DM 64
#define DEPTH 4
#define DTs 0.1f
#define SCALE 0.0625f
#define KSPLIT 2
#define BM 64
#define BN 64
#define NT ((S_TOK/KSPLIT)/BN)   /* 32 key tiles per CTA */
#define SHIFT 20.0f

/* output layout offsets */
#define E_OFF  (S_TOK*DE)
#define P_OFF  (E_OFF + S_TOK)
#define G_OFF  (P_OFF + S_TOK)
#define M_OFF  (G_OFF + S_TOK)
#define C_OFF  (M_OFF + S_TOK*DM)
#define L_OFF  (C_OFF + S_TOK*DM)
#define A_OFF  (L_OFF + S_TOK)
#define D_OFF  (A_OFF + S_TOK)

/* attn SMEM map (bytes) */
#define SQH   0u
#define SQL   32768u
#define SKVH  65536u      /* K tile (64x512B) or V^T tile (256x128B) */
#define SKVL  98304u
#define SMQH  131072u
#define SMQL  139264u
#define SMKH  147456u
#define SMKL  155648u
#define SPH   163840u
#define SPL   172032u
#define SLRED 180224u
#define ATTN_SMEM_BYTES 180736u

/* ------------------------- persistent device state ------------------- */
__device__ float g_e[S_TOK*DE];
__device__ __nv_bfloat16 g_qhi[S_TOK*DE], g_qlo[S_TOK*DE];
__device__ __nv_bfloat16 g_khi[S_TOK*DE], g_klo[S_TOK*DE];
__device__ __nv_bfloat16 g_vthi[DE*S_TOK], g_vtlo[DE*S_TOK];   /* V^T [dim][tok] */
__device__ __nv_bfloat16 g_mthi[S_TOK*DM], g_mtlo[S_TOK*DM];   /* m~ = l*m split */
__device__ float g_m[S_TOK*DM];
__device__ float g_E[S_TOK], g_P[S_TOK], g_G[S_TOK], g_l[S_TOK];
__device__ float g_hpart[KSPLIT][S_TOK*DE];
__device__ float g_Lpart[KSPLIT][S_TOK];
__device__ int   g_alive_count;

/* ------------------------- mma helpers ------------------------------- */
__device__ __forceinline__ uint32_t smem_to_u32(const void* p) {
    uint32_t a;
    asm("{ .reg .u64 t; cvta.to.shared.u64 t, %1; cvt.u32.u64 %0, t; }" : "=r"(a) : "l"(p));
    return a;
}
__device__ __forceinline__ void ldsm4(uint32_t a[4], uint32_t addr) {
    asm volatile("ldmatrix.sync.aligned.m8n8.x4.shared.b16 {%0,%1,%2,%3}, [%4];"
        : "=r"(a[0]), "=r"(a[1]), "=r"(a[2]), "=r"(a[3]) : "r"(addr));
}
__device__ __forceinline__ void mma16816(float c[4], const uint32_t a[4],
                                         uint32_t b0, uint32_t b1) {
    asm volatile("mma.sync.aligned.m16n8k16.row.col.f32.bf16.bf16.f32 "
        "{%0,%1,%2,%3}, {%4,%5,%6,%7}, {%8,%9}, {%0,%1,%2,%3};"
        : "+f"(c[0]), "+f"(c[1]), "+f"(c[2]), "+f"(c[3])
        : "r"(a[0]), "r"(a[1]), "r"(a[2]), "r"(a[3]), "r"(b0), "r"(b1));
}
/* swizzled smem address: rowBytes-stride tile, 16B chunks XORed by row&7 */
__device__ __forceinline__ uint32_t swa(uint32_t base, int r, int colElem, int rowBytes) {
    uint32_t ch = ((uint32_t)colElem >> 3) ^ ((uint32_t)r & 7u);
    return base + (uint32_t)(r * rowBytes) + (ch << 4);
}

/* ------------------------------------------------------------------ init */
__global__ void init_kernel(const float* __restrict__ e, const float* __restrict__ Ein,
                            const float* __restrict__ Pin, const float* __restrict__ Gin,
                            const float* __restrict__ min_, const float* __restrict__ lin)
{
    int i = blockIdx.x * 256 + threadIdx.x;
    g_e[i] = e[i];
    if (i < S_TOK*DM) {
        float mv = min_[i];
        g_m[i] = mv;
        float mt = mv * lin[i / DM];
        __nv_bfloat16 h = __float2bfloat16(mt);
        g_mthi[i] = h;
        g_mtlo[i] = __float2bfloat16(mt - __bfloat162float(h));
    }
    if (i < S_TOK) {
        g_l[i] = lin[i]; g_E[i] = Ein[i]; g_P[i] = Pin[i]; g_G[i] = Gin[i];
    }
    if (i == 0) g_alive_count = 0;
}

/* ------------------------------------------------------- QKV projections */
__global__ void __launch_bounds__(256) qkv_kernel(
    const float* __restrict__ cin,
    const float* __restrict__ wq, const float* __restrict__ bq,
    const float* __restrict__ wk, const float* __restrict__ bk,
    const float* __restrict__ wv, const float* __restrict__ bv, int layer)
{
    __shared__ float sA[16][68];
    __shared__ float sB[16][64];
    __shared__ __nv_bfloat16 sThi[64][80];
    __shared__ __nv_bfloat16 sTlo[64][80];
    const int tid = threadIdx.x;
    const int m0 = blockIdx.x * 64, n0 = blockIdx.y * 64;
    const int which = blockIdx.z;
    const float* W = (which == 0 ? wq : which == 1 ? wk : wv) + (size_t)layer * DIN * DE;
    const float* B = (which == 0 ? bq : which == 1 ? bk : bv) + layer * DE;
    const int ty = tid >> 4, tx = tid & 15;

    float acc[4][4] = {};
    for (int kt = 0; kt < 20; kt++) {
        const int k0 = kt * 16;
        __syncthreads();
        for (int idx = tid; idx < 1024; idx += 256) {
            int mm = idx >> 4, kk = idx & 15;
            float v;
            if (k0 < 256) v = g_e[(m0 + mm) * DE + k0 + kk];
            else          v = cin[(m0 + mm) * DC + (k0 - 256) + kk];
            sA[kk][mm] = v;
        }
        for (int idx = tid; idx < 1024; idx += 256) {
            int kk = idx >> 6, nn = idx & 63;
            sB[kk][nn] = W[(size_t)(k0 + kk) * DE + n0 + nn];
        }
        __syncthreads();
        #pragma unroll
        for (int kk = 0; kk < 16; kk++) {
            float4 a = *(const float4*)&sA[kk][4 * ty];
            float4 b = *(const float4*)&sB[kk][4 * tx];
            acc[0][0] += a.x*b.x; acc[0][1] += a.x*b.y; acc[0][2] += a.x*b.z; acc[0][3] += a.x*b.w;
            acc[1][0] += a.y*b.x; acc[1][1] += a.y*b.y; acc[1][2] += a.y*b.z; acc[1][3] += a.y*b.w;
            acc[2][0] += a.z*b.x; acc[2][1] += a.z*b.y; acc[2][2] += a.z*b.z; acc[2][3] += a.z*b.w;
            acc[3][0] += a.w*b.x; acc[3][1] += a.w*b.y; acc[3][2] += a.w*b.z; acc[3][3] += a.w*b.w;
        }
    }
    if (which < 2) {
        __nv_bfloat16* ohi = (which == 0) ? g_qhi : g_khi;
        __nv_bfloat16* olo = (which == 0) ? g_qlo : g_klo;
        #pragma unroll
        for (int i = 0; i < 4; i++) {
            const int row = m0 + 4*ty + i, col = n0 + 4*tx;
            __nv_bfloat162 h01, h23, l01, l23;
            float v0 = acc[i][0] + B[col+0], v1 = acc[i][1] + B[col+1];
            float v2 = acc[i][2] + B[col+2], v3 = acc[i][3] + B[col+3];
            h01.x = __float2bfloat16(v0); h01.y = __float2bfloat16(v1);
            h23.x = __float2bfloat16(v2); h23.y = __float2bfloat16(v3);
            l01.x = __float2bfloat16(v0 - __bfloat162float(h01.x));
            l01.y = __float2bfloat16(v1 - __bfloat162float(h01.y));
            l23.x = __float2bfloat16(v2 - __bfloat162float(h23.x));
            l23.y = __float2bfloat16(v3 - __bfloat162float(h23.y));
            uint2 uh, ul;
            uh.x = reinterpret_cast<uint32_t&>(h01); uh.y = reinterpret_cast<uint32_t&>(h23);
            ul.x = reinterpret_cast<uint32_t&>(l01); ul.y = reinterpret_cast<uint32_t&>(l23);
            *(uint2*)(ohi + (size_t)row*DE + col) = uh;
            *(uint2*)(olo + (size_t)row*DE + col) = ul;
        }
    } else {
        #pragma unroll
        for (int i = 0; i < 4; i++)
            #pragma unroll
            for (int j = 0; j < 4; j++) {
                float v = acc[i][j] + B[n0 + 4*tx + j];
                __nv_bfloat16 h = __float2bfloat16(v);
                sThi[4*tx + j][4*ty + i] = h;
                sTlo[4*tx + j][4*ty + i] = __float2bfloat16(v - __bfloat162float(h));
            }
        __syncthreads();
        for (int idx = tid; idx < 64*8; idx += 256) {
            int r = idx >> 3, c = (idx & 7) * 8;
            *(uint4*)(g_vthi + (size_t)(n0 + r)*S_TOK + m0 + c) = *(const uint4*)(&sThi[r][c]);
            *(uint4*)(g_vtlo + (size_t)(n0 + r)*S_TOK + m0 + c) = *(const uint4*)(&sTlo[r][c]);
        }
    }
}

/* -------------------------------------------- mma.sync flash attention */
__global__ void __launch_bounds__(256, 1) attn_kernel()
{
    extern __shared__ unsigned char sm[];
    const uint32_t sb = smem_to_u32(sm);
    float* sLred = (float*)(sm + SLRED);

    const int tid = threadIdx.x;
    const int w = tid >> 5, lane = tid & 31;
    const int row0 = blockIdx.x * BM;
    const int ks = blockIdx.y;
    const int key_base = ks * (S_TOK / KSPLIT);

    const int r0 = (w >> 1) * 16;          /* warp's 16 query rows */
    const int halfn = w & 1;               /* score col half / AV dim half */
    const int c0 = halfn * 32;
    const int lr = lane >> 2;              /* acc row within 8 */
    const int qr = (lane & 3) * 2;         /* acc col pair within n8 */
    const int lrow = lane & 15, lkh = (lane >> 4) * 8;

    /* ---- load Q hi/lo (64x512B, swizzled) and m~q (64x128B) ---- */
    for (int idx = tid; idx < 64*32; idx += 256) {
        int r = idx >> 5, ch = idx & 31;
        uint32_t dst = (uint32_t)ch ^ ((uint32_t)r & 7u);
        *(uint4*)(sm + SQH + r*512 + dst*16) = *(const uint4*)(g_qhi + (size_t)(row0 + r)*DE + ch*8);
        *(uint4*)(sm + SQL + r*512 + dst*16) = *(const uint4*)(g_qlo + (size_t)(row0 + r)*DE + ch*8);
    }
    for (int idx = tid; idx < 64*8; idx += 256) {
        int r = idx >> 3, ch = idx & 7;
        uint32_t dst = (uint32_t)ch ^ ((uint32_t)r & 7u);
        *(uint4*)(sm + SMQH + r*128 + dst*16) = *(const uint4*)(g_mthi + (size_t)(row0 + r)*DM + ch*8);
        *(uint4*)(sm + SMQL + r*128 + dst*16) = *(const uint4*)(g_mtlo + (size_t)(row0 + r)*DM + ch*8);
    }

    float avacc[16][4];
    #pragma unroll
    for (int g = 0; g < 16; g++) { avacc[g][0]=0.f; avacc[g][1]=0.f; avacc[g][2]=0.f; avacc[g][3]=0.f; }
    float L0 = 0.f, L1 = 0.f;

    for (int kt = 0; kt < NT; kt++) {
        const int key0 = key_base + kt * BN;
        __syncthreads();   /* prev AV reads done -> safe to overwrite KV, P */

        /* K tile hi/lo + m~k tile */
        for (int idx = tid; idx < 64*32; idx += 256) {
            int r = idx >> 5, ch = idx & 31;
            uint32_t dst = (uint32_t)ch ^ ((uint32_t)r & 7u);
            *(uint4*)(sm + SKVH + r*512 + dst*16) = *(const uint4*)(g_khi + (size_t)(key0 + r)*DE + ch*8);
            *(uint4*)(sm + SKVL + r*512 + dst*16) = *(const uint4*)(g_klo + (size_t)(key0 + r)*DE + ch*8);
        }
        for (int idx = tid; idx < 64*8; idx += 256) {
            int r = idx >> 3, ch = idx & 7;
            uint32_t dst = (uint32_t)ch ^ ((uint32_t)r & 7u);
            *(uint4*)(sm + SMKH + r*128 + dst*16) = *(const uint4*)(g_mthi + (size_t)(key0 + r)*DM + ch*8);
            *(uint4*)(sm + SMKL + r*128 + dst*16) = *(const uint4*)(g_mtlo + (size_t)(key0 + r)*DM + ch*8);
        }
        __syncthreads();

        /* ---- scores: qk (K=256) and mm (K=64), 16 rows x 32 cols ---- */
        float sqk[4][4] = {}, smm[4][4] = {};
        #pragma unroll 1
        for (int kc = 0; kc < 16; kc++) {
            uint32_t ah[4], al[4];
            ldsm4(ah, swa(sb + SQH, r0 + lrow, kc*16 + lkh, 512));
            ldsm4(al, swa(sb + SQL, r0 + lrow, kc*16 + lkh, 512));
            #pragma unroll
            for (int g = 0; g < 2; g++) {
                uint32_t bh[4], bl[4];
                ldsm4(bh, swa(sb + SKVH, c0 + 16*g + lrow, kc*16 + lkh, 512));
                ldsm4(bl, swa(sb + SKVL, c0 + 16*g + lrow, kc*16 + lkh, 512));
                mma16816(sqk[2*g],   ah, bh[0], bh[2]);
                mma16816(sqk[2*g],   ah, bl[0], bl[2]);
                mma16816(sqk[2*g],   al, bh[0], bh[2]);
                mma16816(sqk[2*g+1], ah, bh[1], bh[3]);
                mma16816(sqk[2*g+1], ah, bl[1], bl[3]);
                mma16816(sqk[2*g+1], al, bh[1], bh[3]);
            }
        }
        #pragma unroll 1
        for (int kc = 0; kc < 4; kc++) {
            uint32_t ah[4], al[4];
            ldsm4(ah, swa(sb + SMQH, r0 + lrow, kc*16 + lkh, 128));
            ldsm4(al, swa(sb + SMQL, r0 + lrow, kc*16 + lkh, 128));
            #pragma unroll
            for (int g = 0; g < 2; g++) {
                uint32_t bh[4], bl[4];
                ldsm4(bh, swa(sb + SMKH, c0 + 16*g + lrow, kc*16 + lkh, 128));
                ldsm4(bl, swa(sb + SMKL, c0 + 16*g + lrow, kc*16 + lkh, 128));
                mma16816(smm[2*g],   ah, bh[0], bh[2]);
                mma16816(smm[2*g],   ah, bl[0], bl[2]);
                mma16816(smm[2*g],   al, bh[0], bh[2]);
                mma16816(smm[2*g+1], ah, bh[1], bh[3]);
                mma16816(smm[2*g+1], ah, bl[1], bl[3]);
                mma16816(smm[2*g+1], al, bh[1], bh[3]);
            }
        }

        /* ---- exp + P store (bf16 hi/lo, swizzled 128B rows) ---- */
        {
            const int prow = r0 + lr;
            #pragma unroll
            for (int j = 0; j < 4; j++) {
                float p00 = __expf(sqk[j][0] * SCALE * smm[j][0] - SHIFT);
                float p01 = __expf(sqk[j][1] * SCALE * smm[j][1] - SHIFT);
                float p10 = __expf(sqk[j][2] * SCALE * smm[j][2] - SHIFT);
                float p11 = __expf(sqk[j][3] * SCALE * smm[j][3] - SHIFT);
                L0 += p00 + p01;
                L1 += p10 + p11;
                __nv_bfloat162 h0, l0v, h1, l1v;
                h0.x = __float2bfloat16(p00); h0.y = __float2bfloat16(p01);
                l0v.x = __float2bfloat16(p00 - __bfloat162float(h0.x));
                l0v.y = __float2bfloat16(p01 - __bfloat162float(h0.y));
                h1.x = __float2bfloat16(p10); h1.y = __float2bfloat16(p11);
                l1v.x = __float2bfloat16(p10 - __bfloat162float(h1.x));
                l1v.y = __float2bfloat16(p11 - __bfloat162float(h1.y));
                uint32_t ch = (uint32_t)((c0 >> 3) + j) ^ ((uint32_t)prow & 7u);
                uint32_t o0 = (uint32_t)prow*128 + (ch<<4) + (lane & 3)*4;
                uint32_t o1 = (uint32_t)(prow+8)*128 + (ch<<4) + (lane & 3)*4;
                *(uint32_t*)(sm + SPH + o0) = reinterpret_cast<uint32_t&>(h0);
                *(uint32_t*)(sm + SPL + o0) = reinterpret_cast<uint32_t&>(l0v);
                *(uint32_t*)(sm + SPH + o1) = reinterpret_cast<uint32_t&>(h1);
                *(uint32_t*)(sm + SPL + o1) = reinterpret_cast<uint32_t&>(l1v);
            }
        }
        __syncthreads();   /* P visible; K reads done -> overwrite with V^T */

        /* V^T tile hi/lo (256 dims x 128B) */
        for (int idx = tid; idx < 256*8; idx += 256) {
            int r = idx >> 3, ch = idx & 7;
            uint32_t dst = (uint32_t)ch ^ ((uint32_t)r & 7u);
            *(uint4*)(sm + SKVH + r*128 + dst*16) = *(const uint4*)(g_vthi + (size_t)r*S_TOK + key0 + ch*8);
            *(uint4*)(sm + SKVL + r*128 + dst*16) = *(const uint4*)(g_vtlo + (size_t)r*S_TOK + key0 + ch*8);
        }
        __syncthreads();

        /* ---- AV: 16 rows x 128 dims (this warp's half), K=64 keys ---- */
        #pragma unroll 1
        for (int kc = 0; kc < 4; kc++) {
            uint32_t ah[4], al[4];
            ldsm4(ah, swa(sb + SPH, r0 + lrow, kc*16 + lkh, 128));
            ldsm4(al, swa(sb + SPL, r0 + lrow, kc*16 + lkh, 128));
            #pragma unroll
            for (int gg = 0; gg < 8; gg++) {
                const int dd = halfn*128 + 16*gg;
                uint32_t bh[4], bl[4];
                ldsm4(bh, swa(sb + SKVH, dd + lrow, kc*16 + lkh, 128));
                ldsm4(bl, swa(sb + SKVL, dd + lrow, kc*16 + lkh, 128));
                mma16816(avacc[2*gg],   ah, bh[0], bh[2]);
                mma16816(avacc[2*gg],   ah, bl[0], bl[2]);
                mma16816(avacc[2*gg],   al, bh[0], bh[2]);
                mma16816(avacc[2*gg+1], ah, bh[1], bh[3]);
                mma16816(avacc[2*gg+1], ah, bl[1], bl[3]);
                mma16816(avacc[2*gg+1], al, bh[1], bh[3]);
            }
        }
    }

    /* ---- epilogue: unnormalized partials + L ---- */
    {
        float* hp = g_hpart[ks];
        #pragma unroll
        for (int g = 0; g < 16; g++) {
            const int d = halfn*128 + 8*g + qr;
            *(float2*)(hp + (size_t)(row0 + r0 + lr)*DE + d)     = make_float2(avacc[g][0], avacc[g][1]);
            *(float2*)(hp + (size_t)(row0 + r0 + lr + 8)*DE + d) = make_float2(avacc[g][2], avacc[g][3]);
        }
    }
    L0 += __shfl_xor_sync(0xffffffffu, L0, 1);
    L0 += __shfl_xor_sync(0xffffffffu, L0, 2);
    L1 += __shfl_xor_sync(0xffffffffu, L1, 1);
    L1 += __shfl_xor_sync(0xffffffffu, L1, 2);
    __syncthreads();
    if ((lane & 3) == 0) {
        sLred[halfn*64 + r0 + lr]     = L0;
        sLred[halfn*64 + r0 + lr + 8] = L1;
    }
    __syncthreads();
    if (tid < 64) g_Lpart[ks][row0 + tid] = sLred[tid] + sLred[64 + tid];
}

/* ----------------------------------------- combine splits + ODE update */
__global__ void combine_kernel(const float* __restrict__ alpha, const float* __restrict__ beta,
                               const float* __restrict__ gamma, const float* __restrict__ basal,
                               int layer)
{
    const int s = blockIdx.x, tid = threadIdx.x;
    float Lt = 0.f, num = 0.f;
    #pragma unroll
    for (int k = 0; k < KSPLIT; k++) {
        Lt  += g_Lpart[k][s];
        num += g_hpart[k][(size_t)s*DE + tid];
    }
    const float h = num / Lt;
    g_e[(size_t)s*DE + tid] += h;

    float part = h * h;
    #pragma unroll
    for (int off = 16; off; off >>= 1) part += __shfl_xor_sync(0xffffffffu, part, off);
    __shared__ float red[8];
    __shared__ float sc[2];
    if ((tid & 31) == 0) red[tid >> 5] = part;
    __syncthreads();
    if (tid == 0) {
        float S_in = red[0]+red[1]+red[2]+red[3]+red[4]+red[5]+red[6]+red[7];
        float E = g_E[s], P = g_P[s], Gv = g_G[s], l = g_l[s];
        float PE = P * E;
        float P_new = fmaxf(P + (alpha[layer]*S_in - beta[layer]*PE) * DTs, 0.f);
        float E_new = fmaxf(E + (basal[layer] - gamma[layer]*PE) * DTs, 0.f);
        float m_t = 1.f / (1.f + expf(-(E_new - P_new)));
        Gv += (0.1f*E_new - 0.5f*P_new) * DTs;
        float ldec = 0.01f + 0.5f*fmaxf(P_new - 2.f, 0.f);
        float l_new = fminf(fmaxf(l - ldec*DTs, 0.f), 1.f);
        g_E[s] = E_new; g_P[s] = P_new; g_G[s] = Gv; g_l[s] = l_new;
        sc[0] = m_t; sc[1] = l_new;
    }
    __syncthreads();
    if (tid < DM) {
        float mo = g_m[s*DM + tid];
        float mn = 0.9f*mo + 0.1f*sc[0];
        g_m[s*DM + tid] = mn;
        float mt = sc[1] * mn;
        __nv_bfloat16 hh = __float2bfloat16(mt);
        g_mthi[s*DM + tid] = hh;
        g_mtlo[s*DM + tid] = __float2bfloat16(mt - __bfloat162float(hh));
    }
}

/* -------------------------------------------------------- final output */
__global__ void output_kernel(const float* __restrict__ cin, float* __restrict__ out)
{
    const int s = blockIdx.x, tid = threadIdx.x;
    const float l = g_l[s];
    const bool alive = (l > 0.05f);
    const float af = alive ? 1.f : 0.f;
    out[(size_t)s*DE + tid] = g_e[(size_t)s*DE + tid] * af;
    if (tid < DM) {
        out[M_OFF + s*DM + tid] = g_m[s*DM + tid] * af;
        out[C_OFF + s*DM + tid] = cin[s*DM + tid] * af;
    }
    if (tid == 0) {
        out[E_OFF + s] = g_E[s] * af;
        out[P_OFF + s] = g_P[s] * af;
        out[G_OFF + s] = g_G[s] * af;
        out[L_OFF + s] = l * af;
        out[A_OFF + s] = af;
        if (alive) atomicAdd(&g_alive_count, 1);
    }
}

__global__ void died_kernel(float* __restrict__ out)
{
    out[D_OFF] = (float)(S_TOK - g_alive_count);
}

/* -------------------------------------------------------------- launch */
extern "C" void kernel_launch(void* const* d_in, const int* in_sizes, int n_in,
                              void* d_out, int out_size)
{
    const float* e     = (const float*)d_in[0];
    const float* Ein   = (const float*)d_in[1];
    const float* Pin   = (const float*)d_in[2];
    const float* Gin   = (const float*)d_in[3];
    const float* m     = (const float*)d_in[4];
    const float* c     = (const float*)d_in[5];
    const float* l     = (const float*)d_in[6];
    const float* wq    = (const float*)d_in[7];
    const float* bq    = (const float*)d_in[8];
    const float* wk    = (const float*)d_in[9];
    const float* bk    = (const float*)d_in[10];
    const float* wv    = (const float*)d_in[11];
    const float* bv    = (const float*)d_in[12];
    const float* alpha = (const float*)d_in[13];
    const float* beta  = (const float*)d_in[14];
    const float* gamma = (const float*)d_in[15];
    const float* basal = (const float*)d_in[16];
    float* out = (float*)d_out;

    cudaFuncSetAttribute(attn_kernel, cudaFuncAttributeMaxDynamicSharedMemorySize,
                         ATTN_SMEM_BYTES);

    init_kernel<<<S_TOK*DE/256, 256>>>(e, Ein, Pin, Gin, m, l);
    for (int layer = 0; layer < DEPTH; layer++) {
        qkv_kernel<<<dim3(S_TOK/64, DE/64, 3), 256>>>(c, wq, bq, wk, bk, wv, bv, layer);
        attn_kernel<<<dim3(S_TOK/BM, KSPLIT), 256, ATTN_SMEM_BYTES>>>();
        combine_kernel<<<S_TOK, 256>>>(alpha, beta, gamma, basal, layer);
    }
    output_kernel<<<S_TOK, 256>>>(c, out);
    died_kernel<<<1, 1>>>(out);
}